// round 12
// baseline (speedup 1.0000x reference)
#include <cuda_runtime.h>
#include <cuda_bf16.h>
#include <cstdint>

// ---------------- problem constants ----------------
#define Bc 16
#define Dc 64
#define Tc 8192
#define Kc 512
#define DT (Dc * Tc)        // 524288
#define BT (Bc * Tc)        // 131072
#define THREADS 256
#define GRID 148
#define NTILES (BT / 128)   // 1024 token tiles
#define NKT 12              // K=192 in 12 k-tiles of 16
#define CHUNK_BYTES (128 * 192 * 2)   // 49152 B per 128-codeword chunk
#define WIN 1e-4f           // >> 2*(mma err ~1e-6 + ref grain ~1.2e-5)

// ---------------- smem layout ----------------
#define SM_CN   0                           // 512 f32 norms
#define SM_CS   2048                        // float4 candS[128]
#define SM_CK   4096                        // int4   candK[128]
#define SM_KST  6144                        // int    kst[128]
#define SM_A    6656                        // 128x192 bf16, 16x16 tiles
#define SM_B0   (SM_A + CHUNK_BYTES)        // 55808
#define SM_B1   (SM_B0 + CHUNK_BYTES)       // 104960
#define SMEM_TOTAL (SM_B1 + CHUNK_BYTES)    // 154112 B

__device__ __align__(16) unsigned char g_B[4 * CHUNK_BYTES];
__device__ float g_cn[Kc];

// ---------------- helpers ----------------
__device__ __forceinline__ uint32_t smem_u32(const void* p) {
    uint32_t a;
    asm("{ .reg .u64 t; cvta.to.shared.u64 t, %1; cvt.u32.u64 %0, t; }"
        : "=r"(a) : "l"(p));
    return a;
}

#define LDSM4(r0, r1, r2, r3, addr)                                          \
    asm volatile("ldmatrix.sync.aligned.m8n8.x4.shared.b16 {%0,%1,%2,%3}, [%4];" \
        : "=r"(r0), "=r"(r1), "=r"(r2), "=r"(r3) : "r"(addr))

#define MMA_BF16(c, a0, a1, a2, a3, b0, b1)                                  \
    asm volatile("mma.sync.aligned.m16n8k16.row.col.f32.bf16.bf16.f32 "      \
        "{%0,%1,%2,%3}, {%4,%5,%6,%7}, {%8,%9}, {%0,%1,%2,%3};"              \
        : "+f"((c)[0]), "+f"((c)[1]), "+f"((c)[2]), "+f"((c)[3])             \
        : "r"(a0), "r"(a1), "r"(a2), "r"(a3), "r"(b0), "r"(b1))

// top-4 state as scalars (prefix P), sorted s0<=s1<=s2<=s3; strict < keeps first
#define DEF4(P) float P##s0=3.4e38f, P##s1=3.4e38f, P##s2=3.4e38f, P##s3=3.4e38f; \
                int P##k0=0, P##k1=0, P##k2=0, P##k3=0
#define INS4(P, s, k) do {                                                   \
    float _s = (s); int _k = (k);                                            \
    if (_s < P##s3) {                                                        \
        if (_s < P##s0)      { P##s3=P##s2;P##k3=P##k2; P##s2=P##s1;P##k2=P##k1; P##s1=P##s0;P##k1=P##k0; P##s0=_s;P##k0=_k; } \
        else if (_s < P##s1) { P##s3=P##s2;P##k3=P##k2; P##s2=P##s1;P##k2=P##k1; P##s1=_s;P##k1=_k; } \
        else if (_s < P##s2) { P##s3=P##s2;P##k3=P##k2; P##s2=_s;P##k2=_k; }  \
        else                 { P##s3=_s;P##k3=_k; } } } while (0)
// merge partner's top4 (read all before inserting -- shfl sees pre-merge values)
#define MRG4(P, st) do {                                                     \
    float _m0=__shfl_xor_sync(0xffffffffu, P##s0, st);                       \
    float _m1=__shfl_xor_sync(0xffffffffu, P##s1, st);                       \
    float _m2=__shfl_xor_sync(0xffffffffu, P##s2, st);                       \
    float _m3=__shfl_xor_sync(0xffffffffu, P##s3, st);                       \
    int _n0=__shfl_xor_sync(0xffffffffu, P##k0, st);                         \
    int _n1=__shfl_xor_sync(0xffffffffu, P##k1, st);                         \
    int _n2=__shfl_xor_sync(0xffffffffu, P##k2, st);                         \
    int _n3=__shfl_xor_sync(0xffffffffu, P##k3, st);                         \
    INS4(P,_m0,_n0); INS4(P,_m1,_n1); INS4(P,_m2,_n2); INS4(P,_m3,_n3);      \
} while (0)

__device__ __forceinline__ uint32_t pack_bf16(__nv_bfloat16 a, __nv_bfloat16 b) {
    uint16_t ua = *(uint16_t*)&a, ub = *(uint16_t*)&b;
    return (uint32_t)ua | ((uint32_t)ub << 16);
}

__device__ __forceinline__ void chunk_async(uint32_t sdst, const unsigned char* gsrc,
                                            int tid) {
    #pragma unroll
    for (int i = 0; i < 12; i++) {
        uint32_t s = sdst + (uint32_t)(tid + i * THREADS) * 16;
        const unsigned char* g = gsrc + (size_t)(tid + i * THREADS) * 16;
        asm volatile("cp.async.cg.shared.global [%0], [%1], 16;" :: "r"(s), "l"(g));
    }
    asm volatile("cp.async.commit_group;" ::: "memory");
}
#define CP_WAIT0() asm volatile("cp.async.wait_group 0;" ::: "memory")

// ---------------- prep: bake B (bf16 split [ch,cl,ch]) + cn ----------------
__global__ void vq_prep(const float* __restrict__ cb)
{
    int r = blockIdx.x * blockDim.x + threadIdx.x;
    if (r >= Kc) return;
    const float* row = cb + r * Dc;
    unsigned char* base = g_B + (size_t)(r >> 7) * CHUNK_BYTES;
    const int n8 = (r & 127) >> 3, nr = r & 7;
    float cn = 0.f;
    for (int d = 0; d < Dc; d++) {
        float v = row[d];
        cn = __fadd_rn(cn, __fmul_rn(v, v));     // serial ascending (matches ref)
        __nv_bfloat16 ch = __float2bfloat16_rn(v);
        __nv_bfloat16 cl = __float2bfloat16_rn(v - __bfloat162float(ch));
        const int ks[3] = { d, 64 + d, 128 + d };
        const __nv_bfloat16 vs[3] = { ch, cl, ch };
        #pragma unroll
        for (int j = 0; j < 3; j++) {
            int k = ks[j];
            uint32_t off = (uint32_t)(((k >> 4) * 16 + n8) * 256 + nr * 32 + (k & 15) * 2);
            *(__nv_bfloat16*)(base + off) = vs[j];
        }
    }
    g_cn[r] = cn;
}

// ---------------- main ----------------
__global__ __launch_bounds__(THREADS, 1)
void vq_main(const float* __restrict__ x,
             const float* __restrict__ cb,
             float* __restrict__ out,
             int write_second)
{
    extern __shared__ char smem[];
    const uint32_t sb = smem_u32(smem);
    const int tid = threadIdx.x, wid = tid >> 5, lane = tid & 31;
    float* scn = (float*)(smem + SM_CN);
    float4* candS = (float4*)(smem + SM_CS);
    int4*   candK = (int4*)(smem + SM_CK);
    int*    skst  = (int*)(smem + SM_KST);

    for (int i = tid; i < Kc; i += THREADS) scn[i] = g_cn[i];

    const uint32_t aOff = (uint32_t)(lane & 15) * 32 + (uint32_t)(lane >> 4) * 16;
    const uint32_t bOff = (uint32_t)(lane & 7) * 32 + (uint32_t)((lane >> 3) & 1) * 16
                        + (uint32_t)(lane >> 4) * 256;
    const uint32_t sA = sb + SM_A;
    const uint32_t sBbuf[2] = { sb + SM_B0, sb + SM_B1 };

    // first B0 copy in flight before first tile
    chunk_async(sBbuf[0], g_B, tid);

    for (int tile = blockIdx.x; tile < NTILES; tile += GRID) {
        const int b = tile >> 6, t0 = (tile & 63) * 128;
        const float* xbase = x + (size_t)b * DT + t0;

        // ---- A build: [xh, xh, xl] while B0 copy is in flight ----
        for (int i = tid; i < 128 * 32; i += THREADS) {
            const int tl = i & 127, dp = i >> 7;
            const float v0 = xbase[(size_t)(2 * dp) * Tc + tl];
            const float v1 = xbase[(size_t)(2 * dp + 1) * Tc + tl];
            const __nv_bfloat16 h0 = __float2bfloat16_rn(v0);
            const __nv_bfloat16 h1 = __float2bfloat16_rn(v1);
            const __nv_bfloat16 l0 = __float2bfloat16_rn(v0 - __bfloat162float(h0));
            const __nv_bfloat16 l1 = __float2bfloat16_rn(v1 - __bfloat162float(h1));
            const uint32_t hp = pack_bf16(h0, h1), lp = pack_bf16(l0, l1);
            const uint32_t rowb = (uint32_t)(tl >> 4) * 12 * 512 + (uint32_t)(tl & 15) * 32;
            const int k0 = 2 * dp;
            #pragma unroll
            for (int j = 0; j < 3; j++) {
                const int k = k0 + j * 64;
                const uint32_t val = (j == 2) ? lp : hp;
                *(uint32_t*)(smem + SM_A + rowb + (uint32_t)(k >> 4) * 512
                             + (uint32_t)(k & 15) * 2) = val;
            }
        }

        DEF4(A_);   // row rA = wid*16 + (lane>>2)
        DEF4(B_);   // row rA + 8

        #pragma unroll 1
        for (int c = 0; c < 4; c++) {
            CP_WAIT0();        // B(c) resident
            __syncthreads();   // all warps done with buf[(c+1)&1]'s previous chunk
            // prefetch B((c+1) mod 4) -- same cycle every tile, covers next tile too
            chunk_async(sBbuf[(c + 1) & 1],
                        g_B + (size_t)((c + 1) & 3) * CHUNK_BYTES, tid);

            const uint32_t aW = sA + (uint32_t)wid * NKT * 512 + aOff;
            const uint32_t sB = sBbuf[c & 1] + bOff;
            float acc[16][4];
            #pragma unroll
            for (int t8 = 0; t8 < 16; t8++)
                #pragma unroll
                for (int q = 0; q < 4; q++) acc[t8][q] = 0.f;

            #pragma unroll
            for (int kt = 0; kt < NKT; kt++) {
                uint32_t a0, a1, a2, a3;
                LDSM4(a0, a1, a2, a3, aW + (uint32_t)kt * 512);
                #pragma unroll
                for (int pr = 0; pr < 8; pr++) {
                    uint32_t r0, r1, r2, r3;
                    LDSM4(r0, r1, r2, r3, sB + (uint32_t)(kt * 16 + pr * 2) * 256);
                    MMA_BF16(acc[2 * pr],     a0, a1, a2, a3, r0, r1);
                    MMA_BF16(acc[2 * pr + 1], a0, a1, a2, a3, r2, r3);
                }
            }

            // ---- fragment scan: this thread owns cols 2*(lane&3)+{0,1} per n8 tile ----
            const int kq = c * 128 + 2 * (lane & 3);
            #pragma unroll
            for (int t8 = 0; t8 < 16; t8++) {
                const int k = kq + t8 * 8;
                const float2 cn2 = *(const float2*)(scn + k);
                INS4(A_, fmaf(-2.f, acc[t8][0], cn2.x), k);
                INS4(A_, fmaf(-2.f, acc[t8][1], cn2.y), k + 1);
                INS4(B_, fmaf(-2.f, acc[t8][2], cn2.x), k);
                INS4(B_, fmaf(-2.f, acc[t8][3], cn2.y), k + 1);
            }
        }

        // ---- quad merge: global top4 per row over all 512 ----
        MRG4(A_, 1); MRG4(A_, 2);
        MRG4(B_, 1); MRG4(B_, 2);
        if ((lane & 3) == 0) {
            const int rA = wid * 16 + (lane >> 2);
            candS[rA]     = make_float4(A_s0, A_s1, A_s2, A_s3);
            candK[rA]     = make_int4(A_k0, A_k1, A_k2, A_k3);
            candS[rA + 8] = make_float4(B_s0, B_s1, B_s2, B_s3);
            candK[rA + 8] = make_int4(B_k0, B_k1, B_k2, B_k3);
        }
        __syncthreads();

        // ---- finalize (threads 0..127): window check + exact rescore ----
        if (tid < 128) {
            const float4 cs = candS[tid];
            const int4   ckk = candK[tid];
            const int t = t0 + tid;
            int kstar = ckk.x;
            const float thr = cs.x + WIN;

            if (cs.y <= thr) {
                const float* xp = x + (size_t)b * DT + t;
                float xn = 0.f;
                #pragma unroll
                for (int d = 0; d < Dc; d++) {
                    const float v = xp[(size_t)d * Tc];
                    xn = __fadd_rn(xn, __fmul_rn(v, v));
                }
                float be = 3.4e38f;
                if (cs.w <= thr) {
                    // rare: >3 near-ties -> full exact scan (ascending k, strict <)
                    for (int k = 0; k < Kc; k++) {
                        const float* cr = cb + k * Dc;
                        float dot = 0.f;
                        #pragma unroll
                        for (int d = 0; d < Dc; d++)
                            dot = fmaf(xp[(size_t)d * Tc], __ldg(cr + d), dot);
                        const float s = __fadd_rn(fmaf(-2.f, dot, xn), scn[k]);
                        if (s < be) { be = s; kstar = k; }
                    }
                } else {
                    int nc = 2, ck[4];
                    ck[0] = ckk.x; ck[1] = ckk.y;
                    if (cs.z <= thr) ck[nc++] = ckk.z;
                    #pragma unroll
                    for (int i = 0; i < 2; i++)
                        #pragma unroll
                        for (int j = 0; j < 2; j++)
                            if (j + 1 < nc && ck[j + 1] < ck[j]) {
                                int tk = ck[j]; ck[j] = ck[j + 1]; ck[j + 1] = tk;
                            }
                    for (int i = 0; i < nc; i++) {
                        const int k = ck[i];
                        const float* cr = cb + k * Dc;
                        float dot = 0.f;
                        #pragma unroll
                        for (int d = 0; d < Dc; d++)
                            dot = fmaf(xp[(size_t)d * Tc], __ldg(cr + d), dot);
                        const float s = __fadd_rn(fmaf(-2.f, dot, xn), scn[k]);
                        if (s < be) { be = s; kstar = k; }
                    }
                }
            }
            skst[tid] = kstar;
        }
        __syncthreads();

        // ---- writeback: all 256 threads; half per output copy ----
        {
            const int tt = tid & 127;
            const int half = tid >> 7;
            if (half == 0 || write_second) {
                const int kst = skst[tt];
                const float4* q = (const float4*)(cb + kst * Dc);
                float* o = out + (size_t)b * DT + (t0 + tt)
                         + (size_t)half * ((size_t)Bc * DT);
                #pragma unroll
                for (int g = 0; g < 16; g++) {
                    const float4 v = __ldg(q + g);
                    const size_t r = (size_t)(4 * g) * Tc;
                    o[r] = v.x; o[r + Tc] = v.y; o[r + 2 * Tc] = v.z; o[r + 3 * Tc] = v.w;
                }
            }
        }
        __syncthreads();   // cand/skst/A reuse next tile
    }
}

extern "C" void kernel_launch(void* const* d_in, const int* in_sizes, int n_in,
                              void* d_out, int out_size)
{
    const float* x  = (const float*)d_in[0];   // [16, 64, 8192] fp32
    const float* cb = (const float*)d_in[1];   // [512, 64] fp32
    float* out = (float*)d_out;                // 2 x [16,64,8192]

    static int inited = 0;
    if (!inited) {
        cudaFuncSetAttribute(vq_main, cudaFuncAttributeMaxDynamicSharedMemorySize,
                             SMEM_TOTAL);
        inited = 1;
    }
    const int write_second = (out_size >= 2 * Bc * DT) ? 1 : 0;

    vq_prep<<<4, 128>>>(cb);
    vq_main<<<GRID, THREADS, SMEM_TOTAL>>>(x, cb, out, write_second);
}

// round 13
// speedup vs baseline: 1.3592x; 1.3592x over previous
#include <cuda_runtime.h>
#include <cuda_bf16.h>
#include <cstdint>

// ---------------- problem constants ----------------
#define Bc 16
#define Dc 64
#define Tc 8192
#define Kc 512
#define DT (Dc * Tc)        // 524288
#define BT (Bc * Tc)        // 131072
#define THREADS 512
#define GRID 148
#define NTILES (BT / 128)   // 1024 token tiles
#define NKT 12              // K=192 in 12 k-tiles of 16
#define CHUNK_BYTES (128 * 192 * 2)   // 49152 B per 128-codeword chunk
#define WIN 1e-4f           // >> 2*(mma err ~1e-6) + ref grain ~1.5e-5 + pack err 5e-7

// ---------------- smem layout ----------------
#define SM_CN   0                           // 512 f32 norms
#define SM_CAND 2048                        // uint4 cand[128][2]  (two col-halves)
#define SM_KST  6144                        // int kst[128]
#define SM_A    6656                        // 128x192 bf16, 16x16 tiles (128B aligned)
#define SM_B0   (SM_A + CHUNK_BYTES)        // 55808
#define SM_B1   (SM_B0 + CHUNK_BYTES)       // 104960
#define SMEM_TOTAL (SM_B1 + CHUNK_BYTES)    // 154112 B

__device__ __align__(16) unsigned char g_B[4 * CHUNK_BYTES];
__device__ float g_cn[Kc];

// ---------------- helpers ----------------
__device__ __forceinline__ uint32_t smem_u32(const void* p) {
    uint32_t a;
    asm("{ .reg .u64 t; cvta.to.shared.u64 t, %1; cvt.u32.u64 %0, t; }"
        : "=r"(a) : "l"(p));
    return a;
}

#define LDSM4(r0, r1, r2, r3, addr)                                          \
    asm volatile("ldmatrix.sync.aligned.m8n8.x4.shared.b16 {%0,%1,%2,%3}, [%4];" \
        : "=r"(r0), "=r"(r1), "=r"(r2), "=r"(r3) : "r"(addr))

#define MMA_BF16(c, a0, a1, a2, a3, b0, b1)                                  \
    asm volatile("mma.sync.aligned.m16n8k16.row.col.f32.bf16.bf16.f32 "      \
        "{%0,%1,%2,%3}, {%4,%5,%6,%7}, {%8,%9}, {%0,%1,%2,%3};"              \
        : "+f"((c)[0]), "+f"((c)[1]), "+f"((c)[2]), "+f"((c)[3])             \
        : "r"(a0), "r"(a1), "r"(a2), "r"(a3), "r"(b0), "r"(b1))

// pack score+index: monotone-flipped float in high 23 bits, k in low 9.
// umin order == score order (to ~512 ulp ~ 5e-7, absorbed by WIN).
__device__ __forceinline__ uint32_t packsk(float s, int k) {
    uint32_t u = __float_as_uint(s);
    u = (u & 0x80000000u) ? ~u : (u | 0x80000000u);
    return (u & 0xFFFFFE00u) | (uint32_t)k;
}
__device__ __forceinline__ float unpk(uint32_t m) {
    m &= 0xFFFFFE00u;
    uint32_t u = (m & 0x80000000u) ? (m & 0x7FFFFFFFu) : ~m;
    return __uint_as_float(u);
}

// sorted top-4 of packed u32 (q0<=q1<=q2<=q3), strict <
#define DEF4U(P) uint32_t P##0=0xFFFFFFFFu, P##1=0xFFFFFFFFu, P##2=0xFFFFFFFFu, P##3=0xFFFFFFFFu
#define INS4U(P, vv) do { uint32_t _v=(vv);                                  \
    if (_v < P##3) {                                                         \
        if (_v < P##0)      { P##3=P##2; P##2=P##1; P##1=P##0; P##0=_v; }    \
        else if (_v < P##1) { P##3=P##2; P##2=P##1; P##1=_v; }               \
        else if (_v < P##2) { P##3=P##2; P##2=_v; }                          \
        else                { P##3=_v; } } } while (0)
#define MRG4U(P, st) do {                                                    \
    uint32_t _a=__shfl_xor_sync(0xffffffffu, P##0, st);                      \
    uint32_t _b=__shfl_xor_sync(0xffffffffu, P##1, st);                      \
    uint32_t _c=__shfl_xor_sync(0xffffffffu, P##2, st);                      \
    uint32_t _d=__shfl_xor_sync(0xffffffffu, P##3, st);                      \
    INS4U(P,_a); INS4U(P,_b); INS4U(P,_c); INS4U(P,_d); } while (0)

__device__ __forceinline__ uint32_t pack_bf16(__nv_bfloat16 a, __nv_bfloat16 b) {
    uint16_t ua = *(uint16_t*)&a, ub = *(uint16_t*)&b;
    return (uint32_t)ua | ((uint32_t)ub << 16);
}

__device__ __forceinline__ void chunk_async(uint32_t sdst, const unsigned char* gsrc,
                                            int tid) {
    #pragma unroll
    for (int i = 0; i < 6; i++) {   // 512 thr x 6 x 16B = 48KB
        uint32_t s = sdst + (uint32_t)(tid + i * THREADS) * 16;
        const unsigned char* g = gsrc + (size_t)(tid + i * THREADS) * 16;
        asm volatile("cp.async.cg.shared.global [%0], [%1], 16;" :: "r"(s), "l"(g));
    }
    asm volatile("cp.async.commit_group;" ::: "memory");
}
#define CP_WAIT0() asm volatile("cp.async.wait_group 0;" ::: "memory")

// ---------------- prep: bake B (bf16 split [ch,cl,ch]) + cn ----------------
__global__ void vq_prep(const float* __restrict__ cb)
{
    int r = blockIdx.x * blockDim.x + threadIdx.x;
    if (r >= Kc) return;
    const float* row = cb + r * Dc;
    unsigned char* base = g_B + (size_t)(r >> 7) * CHUNK_BYTES;
    const int n8 = (r & 127) >> 3, nr = r & 7;
    float cn = 0.f;
    for (int d = 0; d < Dc; d++) {
        float v = row[d];
        cn = __fadd_rn(cn, __fmul_rn(v, v));     // serial ascending (matches ref)
        __nv_bfloat16 ch = __float2bfloat16_rn(v);
        __nv_bfloat16 cl = __float2bfloat16_rn(v - __bfloat162float(ch));
        const int ks[3] = { d, 64 + d, 128 + d };
        const __nv_bfloat16 vs[3] = { ch, cl, ch };
        #pragma unroll
        for (int j = 0; j < 3; j++) {
            int k = ks[j];
            uint32_t off = (uint32_t)(((k >> 4) * 16 + n8) * 256 + nr * 32 + (k & 15) * 2);
            *(__nv_bfloat16*)(base + off) = vs[j];
        }
    }
    g_cn[r] = cn;
}

// ---------------- main ----------------
__global__ __launch_bounds__(THREADS, 1)
void vq_main(const float* __restrict__ x,
             const float* __restrict__ cb,
             float* __restrict__ out,
             int write_second)
{
    extern __shared__ char smem[];
    const uint32_t sb = smem_u32(smem);
    const int tid = threadIdx.x, wid = tid >> 5, lane = tid & 31;
    const int mt = wid >> 1, nh = wid & 1;     // M-tile 0..7, N-half 0..1
    float* scn = (float*)(smem + SM_CN);
    uint4* cand = (uint4*)(smem + SM_CAND);    // [row*2 + nh]
    int* skst = (int*)(smem + SM_KST);

    for (int i = tid; i < Kc; i += THREADS) scn[i] = g_cn[i];

    const uint32_t aOff = (uint32_t)(lane & 15) * 32 + (uint32_t)(lane >> 4) * 16;
    const uint32_t bOff = (uint32_t)(lane & 7) * 32 + (uint32_t)((lane >> 3) & 1) * 16
                        + (uint32_t)(lane >> 4) * 256;
    const uint32_t sA = sb + SM_A;
    const uint32_t sBbuf[2] = { sb + SM_B0, sb + SM_B1 };

    chunk_async(sBbuf[0], g_B, tid);

    for (int tile = blockIdx.x; tile < NTILES; tile += GRID) {
        const int b = tile >> 6, t0 = (tile & 63) * 128;
        const float* xbase = x + (size_t)b * DT + t0;

        // ---- A build: [xh, xh, xl] (8 iters/thread) ----
        for (int i = tid; i < 128 * 32; i += THREADS) {
            const int tl = i & 127, dp = i >> 7;
            const float v0 = xbase[(size_t)(2 * dp) * Tc + tl];
            const float v1 = xbase[(size_t)(2 * dp + 1) * Tc + tl];
            const __nv_bfloat16 h0 = __float2bfloat16_rn(v0);
            const __nv_bfloat16 h1 = __float2bfloat16_rn(v1);
            const __nv_bfloat16 l0 = __float2bfloat16_rn(v0 - __bfloat162float(h0));
            const __nv_bfloat16 l1 = __float2bfloat16_rn(v1 - __bfloat162float(h1));
            const uint32_t hp = pack_bf16(h0, h1), lp = pack_bf16(l0, l1);
            const uint32_t rowb = (uint32_t)(tl >> 4) * 12 * 512 + (uint32_t)(tl & 15) * 32;
            const int k0 = 2 * dp;
            #pragma unroll
            for (int j = 0; j < 3; j++) {
                const int k = k0 + j * 64;
                const uint32_t val = (j == 2) ? lp : hp;
                *(uint32_t*)(smem + SM_A + rowb + (uint32_t)(k >> 4) * 512
                             + (uint32_t)(k & 15) * 2) = val;
            }
        }

        DEF4U(qA);   // row mt*16 + (lane>>2)
        DEF4U(qB);   // row + 8

        #pragma unroll 1
        for (int c = 0; c < 4; c++) {
            CP_WAIT0();
            __syncthreads();
            chunk_async(sBbuf[(c + 1) & 1],
                        g_B + (size_t)((c + 1) & 3) * CHUNK_BYTES, tid);

            const uint32_t aW = sA + (uint32_t)mt * NKT * 512 + aOff;
            const uint32_t sB = sBbuf[c & 1] + bOff;
            float acc[8][4];
            #pragma unroll
            for (int a = 0; a < 8; a++)
                #pragma unroll
                for (int q = 0; q < 4; q++) acc[a][q] = 0.f;

            #pragma unroll
            for (int kt = 0; kt < NKT; kt++) {
                uint32_t a0, a1, a2, a3;
                LDSM4(a0, a1, a2, a3, aW + (uint32_t)kt * 512);
                #pragma unroll
                for (int pr = 0; pr < 4; pr++) {
                    uint32_t r0, r1, r2, r3;
                    LDSM4(r0, r1, r2, r3,
                          sB + (uint32_t)(kt * 16 + nh * 8 + pr * 2) * 256);
                    MMA_BF16(acc[2 * pr],     a0, a1, a2, a3, r0, r1);
                    MMA_BF16(acc[2 * pr + 1], a0, a1, a2, a3, r2, r3);
                }
            }

            // ---- fragment scan: acc[a] covers n8-tile nh*8+a ----
            const int kq = c * 128 + nh * 64 + 2 * (lane & 3);
            #pragma unroll
            for (int a = 0; a < 8; a++) {
                const int k = kq + a * 8;
                const float2 cn2 = *(const float2*)(scn + k);
                INS4U(qA, packsk(fmaf(-2.f, acc[a][0], cn2.x), k));
                INS4U(qA, packsk(fmaf(-2.f, acc[a][1], cn2.y), k + 1));
                INS4U(qB, packsk(fmaf(-2.f, acc[a][2], cn2.x), k));
                INS4U(qB, packsk(fmaf(-2.f, acc[a][3], cn2.y), k + 1));
            }
        }

        // ---- quad merge -> per-row-half top4 ----
        MRG4U(qA, 1); MRG4U(qA, 2);
        MRG4U(qB, 1); MRG4U(qB, 2);
        if ((lane & 3) == 0) {
            const int rA = mt * 16 + (lane >> 2);
            cand[rA * 2 + nh]       = make_uint4(qA0, qA1, qA2, qA3);
            cand[(rA + 8) * 2 + nh] = make_uint4(qB0, qB1, qB2, qB3);
        }
        __syncthreads();

        // ---- finalize (threads 0..127): merge halves, window, exact rescore ----
        if (tid < 128) {
            const uint4 u = cand[tid * 2], v = cand[tid * 2 + 1];
            uint32_t q0 = u.x, q1 = u.y, q2 = u.z, q3 = u.w;
            INS4U(q, v.x); INS4U(q, v.y); INS4U(q, v.z); INS4U(q, v.w);

            const int t = t0 + tid;
            int kstar = (int)(q0 & 511u);
            const float thr = unpk(q0) + WIN;

            if (unpk(q1) <= thr) {
                const float* xp = x + (size_t)b * DT + t;
                float xn = 0.f;
                #pragma unroll
                for (int d = 0; d < Dc; d++) {
                    const float vv = xp[(size_t)d * Tc];
                    xn = __fadd_rn(xn, __fmul_rn(vv, vv));
                }
                float be = 3.4e38f;
                if (unpk(q3) <= thr) {
                    // rare: 4+ near-ties -> full exact scan (ascending k, strict <)
                    for (int k = 0; k < Kc; k++) {
                        const float* cr = cb + k * Dc;
                        float dot = 0.f;
                        #pragma unroll
                        for (int d = 0; d < Dc; d++)
                            dot = fmaf(xp[(size_t)d * Tc], __ldg(cr + d), dot);
                        const float s = __fadd_rn(fmaf(-2.f, dot, xn), scn[k]);
                        if (s < be) { be = s; kstar = k; }
                    }
                } else {
                    int nc = 2, ck[4];
                    ck[0] = (int)(q0 & 511u); ck[1] = (int)(q1 & 511u);
                    if (unpk(q2) <= thr) ck[nc++] = (int)(q2 & 511u);
                    #pragma unroll
                    for (int i = 0; i < 2; i++)
                        #pragma unroll
                        for (int j = 0; j < 2; j++)
                            if (j + 1 < nc && ck[j + 1] < ck[j]) {
                                int tk = ck[j]; ck[j] = ck[j + 1]; ck[j + 1] = tk;
                            }
                    for (int i = 0; i < nc; i++) {
                        const int k = ck[i];
                        const float* cr = cb + k * Dc;
                        float dot = 0.f;
                        #pragma unroll
                        for (int d = 0; d < Dc; d++)
                            dot = fmaf(xp[(size_t)d * Tc], __ldg(cr + d), dot);
                        const float s = __fadd_rn(fmaf(-2.f, dot, xn), scn[k]);
                        if (s < be) { be = s; kstar = k; }
                    }
                }
            }
            skst[tid] = kstar;
        }
        __syncthreads();

        // ---- writeback: 4 groups of 128 (token, output-copy, d-half) ----
        {
            const int tt = tid & 127;
            const int grp = tid >> 7;          // 0..3
            const int half = grp >> 1;         // output copy
            const int gh = grp & 1;            // d-half (g 0-7 / 8-15)
            if (half == 0 || write_second) {
                const int kst = skst[tt];
                const float4* q = (const float4*)(cb + kst * Dc) + gh * 8;
                float* o = out + (size_t)b * DT + (t0 + tt)
                         + (size_t)half * ((size_t)Bc * DT);
                #pragma unroll
                for (int g = 0; g < 8; g++) {
                    const float4 vv = __ldg(q + g);
                    const size_t r = (size_t)(4 * (gh * 8 + g)) * Tc;
                    o[r] = vv.x; o[r + Tc] = vv.y; o[r + 2 * Tc] = vv.z; o[r + 3 * Tc] = vv.w;
                }
            }
        }
        __syncthreads();
    }
}

extern "C" void kernel_launch(void* const* d_in, const int* in_sizes, int n_in,
                              void* d_out, int out_size)
{
    const float* x  = (const float*)d_in[0];   // [16, 64, 8192] fp32
    const float* cb = (const float*)d_in[1];   // [512, 64] fp32
    float* out = (float*)d_out;                // 2 x [16,64,8192]

    static int inited = 0;
    if (!inited) {
        cudaFuncSetAttribute(vq_main, cudaFuncAttributeMaxDynamicSharedMemorySize,
                             SMEM_TOTAL);
        inited = 1;
    }
    const int write_second = (out_size >= 2 * Bc * DT) ? 1 : 0;

    vq_prep<<<4, 128>>>(cb);
    vq_main<<<GRID, THREADS, SMEM_TOTAL>>>(x, cb, out, write_second);
}

// round 14
// speedup vs baseline: 1.5559x; 1.1447x over previous
#include <cuda_runtime.h>
#include <cuda_bf16.h>
#include <cstdint>

// ---------------- problem constants ----------------
#define Bc 16
#define Dc 64
#define Tc 8192
#define Kc 512
#define DT (Dc * Tc)        // 524288
#define BT (Bc * Tc)        // 131072
#define THREADS 512
#define GRID 148
#define NTILES (BT / 128)   // 1024 token tiles
#define CHUNK_BYTES (128 * 192 * 2)   // 49152 B per 128-codeword B chunk
#define WIN 1e-4f           // >> 2*(mma err ~1e-6) + ref grain ~1.5e-5 + pack err 5e-7

// ---------------- smem layout ----------------
#define SM_CN   0                            // 512 f32 norms
#define SM_CAND 2048                         // uint4 cand[128][2]
#define SM_KST  6144                         // int kst[128]
#define SM_A    6656                         // 128 tok x 128 k bf16 [xh|xl], 16x16 tiles
#define SM_B0   (SM_A + 32768)               // 39424 (static chunk 0)
#define SM_B1   (SM_B0 + CHUNK_BYTES)        // 88576 (static chunk 1)
#define SM_C    (SM_B1 + CHUNK_BYTES)        // 137728 (stream buffer: chunk 2/3)
#define SMEM_TOTAL (SM_C + CHUNK_BYTES)      // 186880 B (~182.5 KB)

__device__ __align__(16) unsigned char g_B[4 * CHUNK_BYTES];
__device__ float g_cn[Kc];

// ---------------- helpers ----------------
__device__ __forceinline__ uint32_t smem_u32(const void* p) {
    uint32_t a;
    asm("{ .reg .u64 t; cvta.to.shared.u64 t, %1; cvt.u32.u64 %0, t; }"
        : "=r"(a) : "l"(p));
    return a;
}

#define LDSM4(r0, r1, r2, r3, addr)                                          \
    asm volatile("ldmatrix.sync.aligned.m8n8.x4.shared.b16 {%0,%1,%2,%3}, [%4];" \
        : "=r"(r0), "=r"(r1), "=r"(r2), "=r"(r3) : "r"(addr))

#define MMA_BF16(c, a0, a1, a2, a3, b0, b1)                                  \
    asm volatile("mma.sync.aligned.m16n8k16.row.col.f32.bf16.bf16.f32 "      \
        "{%0,%1,%2,%3}, {%4,%5,%6,%7}, {%8,%9}, {%0,%1,%2,%3};"              \
        : "+f"((c)[0]), "+f"((c)[1]), "+f"((c)[2]), "+f"((c)[3])             \
        : "r"(a0), "r"(a1), "r"(a2), "r"(a3), "r"(b0), "r"(b1))

// packed score|idx: monotone-flipped float in high 23 bits, k in low 9 bits.
__device__ __forceinline__ uint32_t packsk(float s, int k) {
    uint32_t u = __float_as_uint(s);
    u = (u & 0x80000000u) ? ~u : (u | 0x80000000u);
    return (u & 0xFFFFFE00u) | (uint32_t)k;
}
__device__ __forceinline__ float unpk(uint32_t m) {
    m &= 0xFFFFFE00u;
    uint32_t u = (m & 0x80000000u) ? (m & 0x7FFFFFFFu) : ~m;
    return __uint_as_float(u);
}

// sorted top-4 packed u32 array q[0..3]
#define INS4A(q, vv) do { uint32_t _v = (vv);                                \
    if (_v < (q)[3]) {                                                       \
        if (_v < (q)[0])      { (q)[3]=(q)[2]; (q)[2]=(q)[1]; (q)[1]=(q)[0]; (q)[0]=_v; } \
        else if (_v < (q)[1]) { (q)[3]=(q)[2]; (q)[2]=(q)[1]; (q)[1]=_v; }   \
        else if (_v < (q)[2]) { (q)[3]=(q)[2]; (q)[2]=_v; }                  \
        else                  { (q)[3]=_v; } } } while (0)
#define MRG4A(q, st) do {                                                    \
    uint32_t _a=__shfl_xor_sync(0xffffffffu, (q)[0], st);                    \
    uint32_t _b=__shfl_xor_sync(0xffffffffu, (q)[1], st);                    \
    uint32_t _c=__shfl_xor_sync(0xffffffffu, (q)[2], st);                    \
    uint32_t _d=__shfl_xor_sync(0xffffffffu, (q)[3], st);                    \
    INS4A(q,_a); INS4A(q,_b); INS4A(q,_c); INS4A(q,_d); } while (0)

__device__ __forceinline__ uint32_t pack_bf16(__nv_bfloat16 a, __nv_bfloat16 b) {
    uint16_t ua = *(uint16_t*)&a, ub = *(uint16_t*)&b;
    return (uint32_t)ua | ((uint32_t)ub << 16);
}

__device__ __forceinline__ void chunk_async(uint32_t sdst, const unsigned char* gsrc,
                                            int tid) {
    #pragma unroll
    for (int i = 0; i < 6; i++) {   // 512 thr x 6 x 16B = 48KB
        uint32_t s = sdst + (uint32_t)(tid + i * THREADS) * 16;
        const unsigned char* g = gsrc + (size_t)(tid + i * THREADS) * 16;
        asm volatile("cp.async.cg.shared.global [%0], [%1], 16;" :: "r"(s), "l"(g));
    }
    asm volatile("cp.async.commit_group;" ::: "memory");
}
#define CP_WAIT0() asm volatile("cp.async.wait_group 0;" ::: "memory")

// ---------------- prep: bake B (bf16 split [ch,cl,ch]) + cn ----------------
__global__ void vq_prep(const float* __restrict__ cb)
{
    int r = blockIdx.x * blockDim.x + threadIdx.x;
    if (r >= Kc) return;
    const float* row = cb + r * Dc;
    unsigned char* base = g_B + (size_t)(r >> 7) * CHUNK_BYTES;
    const int n8 = (r & 127) >> 3, nr = r & 7;
    float cn = 0.f;
    for (int d = 0; d < Dc; d++) {
        float v = row[d];
        cn = __fadd_rn(cn, __fmul_rn(v, v));     // serial ascending (matches ref)
        __nv_bfloat16 ch = __float2bfloat16_rn(v);
        __nv_bfloat16 cl = __float2bfloat16_rn(v - __bfloat162float(ch));
        const int ks[3] = { d, 64 + d, 128 + d };
        const __nv_bfloat16 vs[3] = { ch, cl, ch };
        #pragma unroll
        for (int j = 0; j < 3; j++) {
            int k = ks[j];
            uint32_t off = (uint32_t)(((k >> 4) * 16 + n8) * 256 + nr * 32 + (k & 15) * 2);
            *(__nv_bfloat16*)(base + off) = vs[j];
        }
    }
    g_cn[r] = cn;
}

// ---------------- per-chunk compute: 12 ktB with A-frag reuse ----------------
// sB = chunk base + nh*2048 + bOff; kq = chunk*128 + nh*64 + 2*(lane&3)
__device__ __forceinline__ void do_chunk(uint32_t sB, int kq,
                                         const uint32_t (&afr)[8][4],
                                         const float* scn,
                                         uint32_t (&qA)[4], uint32_t (&qB)[4])
{
    float acc[8][4];
    #pragma unroll
    for (int a = 0; a < 8; a++)
        #pragma unroll
        for (int j = 0; j < 4; j++) acc[a][j] = 0.f;

    #pragma unroll
    for (int kt = 0; kt < 12; kt++) {
        const int ka = (kt & 3) + ((kt >> 3) << 2);   // B blocks [ch|cl|ch] -> A [xh|xh|xl]
        #pragma unroll
        for (int pr = 0; pr < 4; pr++) {
            uint32_t r0, r1, r2, r3;
            LDSM4(r0, r1, r2, r3, sB + (uint32_t)(kt * 16 + pr * 2) * 256);
            MMA_BF16(acc[2 * pr],     afr[ka][0], afr[ka][1], afr[ka][2], afr[ka][3], r0, r1);
            MMA_BF16(acc[2 * pr + 1], afr[ka][0], afr[ka][1], afr[ka][2], afr[ka][3], r2, r3);
        }
    }
    #pragma unroll
    for (int a = 0; a < 8; a++) {
        const int k = kq + a * 8;
        const float2 cn2 = *(const float2*)(scn + k);
        INS4A(qA, packsk(fmaf(-2.f, acc[a][0], cn2.x), k));
        INS4A(qA, packsk(fmaf(-2.f, acc[a][1], cn2.y), k + 1));
        INS4A(qB, packsk(fmaf(-2.f, acc[a][2], cn2.x), k));
        INS4A(qB, packsk(fmaf(-2.f, acc[a][3], cn2.y), k + 1));
    }
}

// ---------------- main ----------------
__global__ __launch_bounds__(THREADS, 1)
void vq_main(const float* __restrict__ x,
             const float* __restrict__ cb,
             float* __restrict__ out,
             int write_second)
{
    extern __shared__ char smem[];
    const uint32_t sb = smem_u32(smem);
    const int tid = threadIdx.x, wid = tid >> 5, lane = tid & 31;
    const int mt = wid >> 1, nh = wid & 1;     // M-tile 0..7, N-half 0..1
    float* scn = (float*)(smem + SM_CN);
    uint4* cand = (uint4*)(smem + SM_CAND);
    int* skst = (int*)(smem + SM_KST);

    for (int i = tid; i < Kc; i += THREADS) scn[i] = g_cn[i];

    const uint32_t aOff = (uint32_t)(lane & 15) * 32 + (uint32_t)(lane >> 4) * 16;
    const uint32_t bOff = (uint32_t)(lane & 7) * 32 + (uint32_t)((lane >> 3) & 1) * 16
                        + (uint32_t)(lane >> 4) * 256 + (uint32_t)nh * 2048;
    const uint32_t sA = sb + SM_A;

    // static B0, B1 once; stream buffer C starts with chunk 2
    chunk_async(sb + SM_B0, g_B, tid);
    chunk_async(sb + SM_B1, g_B + CHUNK_BYTES, tid);
    chunk_async(sb + SM_C,  g_B + 2 * CHUNK_BYTES, tid);
    int P = 2;   // chunk id resident in C

    for (int tile = blockIdx.x; tile < NTILES; tile += GRID) {
        const int b = tile >> 6, t0 = (tile & 63) * 128;
        const float* xbase = x + (size_t)b * DT + t0;

        // ---- A build: [xh | xl] 128x128, STS.128 (2 iters/thread) ----
        #pragma unroll
        for (int j = 0; j < 2; j++) {
            const int i = tid + j * THREADS;
            const int tl = i & 127, o = i >> 7;        // d-octet 0..7
            float v[8];
            #pragma unroll
            for (int e = 0; e < 8; e++) v[e] = xbase[(size_t)(o * 8 + e) * Tc + tl];
            uint4 hp, lp;
            {
                uint32_t h[4], l[4];
                #pragma unroll
                for (int p = 0; p < 4; p++) {
                    __nv_bfloat16 h0 = __float2bfloat16_rn(v[2 * p]);
                    __nv_bfloat16 h1 = __float2bfloat16_rn(v[2 * p + 1]);
                    __nv_bfloat16 l0 = __float2bfloat16_rn(v[2 * p]     - __bfloat162float(h0));
                    __nv_bfloat16 l1 = __float2bfloat16_rn(v[2 * p + 1] - __bfloat162float(h1));
                    h[p] = pack_bf16(h0, h1);
                    l[p] = pack_bf16(l0, l1);
                }
                hp = make_uint4(h[0], h[1], h[2], h[3]);
                lp = make_uint4(l[0], l[1], l[2], l[3]);
            }
            const uint32_t base = (uint32_t)((tl >> 4) * 8 + (o >> 1)) * 512
                                + (uint32_t)(tl & 15) * 32 + (uint32_t)(o & 1) * 16;
            *(uint4*)(smem + SM_A + base)            = hp;   // xh at kt = o>>1
            *(uint4*)(smem + SM_A + base + 4 * 512)  = lp;   // xl at kt = 4 + (o>>1)
        }
        CP_WAIT0();          // C (chunk P) + A prerequisites
        __syncthreads();

        // ---- A fragments once per tile (reused by all 4 chunks) ----
        uint32_t afr[8][4];
        #pragma unroll
        for (int kt = 0; kt < 8; kt++)
            LDSM4(afr[kt][0], afr[kt][1], afr[kt][2], afr[kt][3],
                  sA + (uint32_t)(mt * 8 + kt) * 512 + aOff);

        uint32_t qA[4] = {0xFFFFFFFFu, 0xFFFFFFFFu, 0xFFFFFFFFu, 0xFFFFFFFFu};
        uint32_t qB[4] = {0xFFFFFFFFu, 0xFFFFFFFFu, 0xFFFFFFFFu, 0xFFFFFFFFu};
        const int kqL = nh * 64 + 2 * (lane & 3);

        // chunk P (in C)
        do_chunk(sb + SM_C + bOff, P * 128 + kqL, afr, scn, qA, qB);
        __syncthreads();                       // all warps done reading C
        chunk_async(sb + SM_C, g_B + (size_t)(5 - P) * CHUNK_BYTES, tid);

        // static chunks 0, 1 — no barriers, stream load hides behind them
        do_chunk(sb + SM_B0 + bOff, 0   + kqL, afr, scn, qA, qB);
        do_chunk(sb + SM_B1 + bOff, 128 + kqL, afr, scn, qA, qB);

        CP_WAIT0();
        __syncthreads();
        do_chunk(sb + SM_C + bOff, (5 - P) * 128 + kqL, afr, scn, qA, qB);
        P = 5 - P;                             // next tile's first chunk already resident

        // ---- quad merge -> per-row-half top4 ----
        MRG4A(qA, 1); MRG4A(qA, 2);
        MRG4A(qB, 1); MRG4A(qB, 2);
        if ((lane & 3) == 0) {
            const int rA = mt * 16 + (lane >> 2);
            cand[rA * 2 + nh]       = make_uint4(qA[0], qA[1], qA[2], qA[3]);
            cand[(rA + 8) * 2 + nh] = make_uint4(qB[0], qB[1], qB[2], qB[3]);
        }
        __syncthreads();

        // ---- finalize (threads 0..127): merge halves, window, exact rescore ----
        if (tid < 128) {
            const uint4 u = cand[tid * 2], v = cand[tid * 2 + 1];
            uint32_t q[4] = { u.x, u.y, u.z, u.w };
            INS4A(q, v.x); INS4A(q, v.y); INS4A(q, v.z); INS4A(q, v.w);

            const int t = t0 + tid;
            int kstar = (int)(q[0] & 511u);
            const float thr = unpk(q[0]) + WIN;

            if (unpk(q[1]) <= thr) {
                const float* xp = x + (size_t)b * DT + t;
                float xn = 0.f;
                #pragma unroll
                for (int d = 0; d < Dc; d++) {
                    const float vv = xp[(size_t)d * Tc];
                    xn = __fadd_rn(xn, __fmul_rn(vv, vv));
                }
                float be = 3.4e38f;
                if (unpk(q[3]) <= thr) {
                    // rare: 4+ near-ties -> full exact scan (ascending k, strict <)
                    for (int k = 0; k < Kc; k++) {
                        const float* cr = cb + k * Dc;
                        float dot = 0.f;
                        #pragma unroll
                        for (int d = 0; d < Dc; d++)
                            dot = fmaf(xp[(size_t)d * Tc], __ldg(cr + d), dot);
                        const float s = __fadd_rn(fmaf(-2.f, dot, xn), scn[k]);
                        if (s < be) { be = s; kstar = k; }
                    }
                } else {
                    int nc = 2, ck[4];
                    ck[0] = (int)(q[0] & 511u); ck[1] = (int)(q[1] & 511u);
                    if (unpk(q[2]) <= thr) ck[nc++] = (int)(q[2] & 511u);
                    #pragma unroll
                    for (int i = 0; i < 2; i++)
                        #pragma unroll
                        for (int j = 0; j < 2; j++)
                            if (j + 1 < nc && ck[j + 1] < ck[j]) {
                                int tk = ck[j]; ck[j] = ck[j + 1]; ck[j + 1] = tk;
                            }
                    for (int i = 0; i < nc; i++) {
                        const int k = ck[i];
                        const float* cr = cb + k * Dc;
                        float dot = 0.f;
                        #pragma unroll
                        for (int d = 0; d < Dc; d++)
                            dot = fmaf(xp[(size_t)d * Tc], __ldg(cr + d), dot);
                        const float s = __fadd_rn(fmaf(-2.f, dot, xn), scn[k]);
                        if (s < be) { be = s; kstar = k; }
                    }
                }
            }
            skst[tid] = kstar;
        }
        __syncthreads();

        // ---- writeback: 4 groups of 128 (token, output-copy, d-half) ----
        {
            const int tt = tid & 127;
            const int grp = tid >> 7;
            const int half = grp >> 1;
            const int gh = grp & 1;
            if (half == 0 || write_second) {
                const int kst = skst[tt];
                const float4* q4 = (const float4*)(cb + kst * Dc) + gh * 8;
                float* o = out + (size_t)b * DT + (t0 + tt)
                         + (size_t)half * ((size_t)Bc * DT);
                #pragma unroll
                for (int g = 0; g < 8; g++) {
                    const float4 vv = __ldg(q4 + g);
                    const size_t r = (size_t)(4 * (gh * 8 + g)) * Tc;
                    o[r] = vv.x; o[r + Tc] = vv.y; o[r + 2 * Tc] = vv.z; o[r + 3 * Tc] = vv.w;
                }
            }
        }
        __syncthreads();
    }
}

extern "C" void kernel_launch(void* const* d_in, const int* in_sizes, int n_in,
                              void* d_out, int out_size)
{
    const float* x  = (const float*)d_in[0];   // [16, 64, 8192] fp32
    const float* cb = (const float*)d_in[1];   // [512, 64] fp32
    float* out = (float*)d_out;                // 2 x [16,64,8192]

    static int inited = 0;
    if (!inited) {
        cudaFuncSetAttribute(vq_main, cudaFuncAttributeMaxDynamicSharedMemorySize,
                             SMEM_TOTAL);
        inited = 1;
    }
    const int write_second = (out_size >= 2 * Bc * DT) ? 1 : 0;

    vq_prep<<<4, 128>>>(cb);
    vq_main<<<GRID, THREADS, SMEM_TOTAL>>>(x, cb, out, write_second);
}